// round 17
// baseline (speedup 1.0000x reference)
#include <cuda_runtime.h>
#include <cuda_fp16.h>
#include <cstdint>
#include <cstddef>

// Problem constants (fixed: N_VERT=2048, NF=8, order=16, LMAX=2 -> a1=a2=1)
constexpr int    N      = 2048;
constexpr size_t NN     = (size_t)N * N;
constexpr int    NFILT  = 8;
constexpr int    NCOEF  = 17;
constexpr double PI     = 3.14159265358979323846;

// Per-plane fp16 hi/lo storage: planes k=1..16, H_k then L_k.
// H_k at (2(k-1))*NN, L_k at (2(k-1)+1)*NN. T_k == H_k + L_k (to ~2^-22 rel).
__device__ __half g_planes[(size_t)32 * NN];
__device__ float  g_c[NCOEF * NFILT];

__device__ __forceinline__ const __half* planeH(const __half* base, int k) {
    return base + (size_t)(2 * (k - 1)) * NN;
}
__device__ __forceinline__ const __half* planeL(const __half* base, int k) {
    return base + (size_t)(2 * (k - 1) + 1) * NN;
}

// ---------------------------------------------------------------------------
// helpers
// ---------------------------------------------------------------------------
__device__ __forceinline__ uint32_t smem_to_u32(const void* p) {
    uint32_t a;
    asm("{ .reg .u64 t; cvta.to.shared.u64 t, %1; cvt.u32.u64 %0, t; }" : "=r"(a) : "l"(p));
    return a;
}
#define CP_ASYNC16(dst, src) \
    asm volatile("cp.async.cg.shared.global [%0], [%1], 16;" :: "r"(dst), "l"(src) : "memory")
#define CP_COMMIT() asm volatile("cp.async.commit_group;" ::: "memory")
#define CP_WAIT(n)  asm volatile("cp.async.wait_group %0;" :: "n"(n) : "memory")

#define MMA_F16(c, a, b) \
    asm volatile("mma.sync.aligned.m16n8k16.row.col.f32.f16.f16.f32 " \
        "{%0,%1,%2,%3}, {%4,%5,%6,%7}, {%8,%9}, {%0,%1,%2,%3};" \
        : "+f"((c)[0]), "+f"((c)[1]), "+f"((c)[2]), "+f"((c)[3]) \
        : "r"((a)[0]), "r"((a)[1]), "r"((a)[2]), "r"((a)[3]), \
          "r"((b)[0]), "r"((b)[1]))

#define LDSM_X4(r, addr) \
    asm volatile("ldmatrix.sync.aligned.m8n8.x4.shared.b16 {%0,%1,%2,%3}, [%4];" \
        : "=r"((r)[0]), "=r"((r)[1]), "=r"((r)[2]), "=r"((r)[3]) : "r"(addr))

// ---------------------------------------------------------------------------
// coeff kernel
// ---------------------------------------------------------------------------
__global__ void coeff_kernel(const float* __restrict__ taus) {
    int t = threadIdx.x;
    if (t >= NCOEF * NFILT) return;
    int k = t / NFILT, f = t % NFILT;
    double tau = (double)taus[f];
    double s = 0.0;
    for (int j = 0; j < NCOEF; ++j) {
        double jj = (double)j + 0.5;
        double pt = cos(PI * jj / (double)NCOEF) + 1.0;
        s += cos(PI * (double)k * jj / (double)NCOEF) * exp(-pt * tau);
    }
    g_c[k * NFILT + f] = (float)(s * 2.0 / (double)NCOEF);
}

// ---------------------------------------------------------------------------
// init: plane 1 = fp16 hi/lo split of M = L - I (no fp32 archive)
// ---------------------------------------------------------------------------
__global__ void init_split_kernel(const float* __restrict__ L, __half* __restrict__ HP) {
    size_t base = ((size_t)blockIdx.x * blockDim.x + threadIdx.x) * 4;
    if (base >= NN) return;
    size_t row = base / N, col0 = base % N;
    float4 v = *reinterpret_cast<const float4*>(L + base);
    float4 id = make_float4(0.f, 0.f, 0.f, 0.f);
    if (row >= col0 && row < col0 + 4) (&id.x)[row - col0] = 1.0f;
    float4 m = make_float4(v.x - id.x, v.y - id.y, v.z - id.z, v.w - id.w);

    __half h[4], l[4];
    #pragma unroll
    for (int i = 0; i < 4; ++i) {
        float x = (&m.x)[i];
        h[i] = __float2half_rn(x);
        l[i] = __float2half_rn(x - __half2float(h[i]));
    }
    __half* H1 = HP;            // plane 1 H
    __half* L1 = HP + NN;       // plane 1 L
    *reinterpret_cast<half2*>(H1 + base)     = __halves2half2(h[0], h[1]);
    *reinterpret_cast<half2*>(H1 + base + 2) = __halves2half2(h[2], h[3]);
    *reinterpret_cast<half2*>(L1 + base)     = __halves2half2(l[0], l[1]);
    *reinterpret_cast<half2*>(L1 + base + 2) = __halves2half2(l[2], l[3]);
}

// ---------------------------------------------------------------------------
// 3xFP16 GEMM step on UPPER-TRIANGULAR block set (C is symmetric).
// BM=BN=128, BK=32, 512 threads (16 warps 4x4), warp tile 32x32.
// 4-stage cp.async pipeline, ONE barrier per iter, term-major MMA order.
// Mainloop is byte-identical to the proven round-6 config.
// T_old read as Hold+Lold (fp16 pair); TOLD_IS_I=1 (step 2): T_old = I analytic.
// Output: H/L fp16 split ONLY (no fp32 archive). Mirror via smem transpose.
// ---------------------------------------------------------------------------
constexpr int BM = 128;
constexpr int BK = 32;
constexpr int NITER = N / BK;                  // 64
constexpr int RS    = 40;                      // halves per smem row
constexpr uint32_t TILE_BYTES  = 128 * RS * 2; // 10240
constexpr uint32_t STAGE_BYTES = 4 * TILE_BYTES;     // 40960
constexpr uint32_t SMEM_BYTES  = 4 * STAGE_BYTES;    // 163840
constexpr int RS2 = 129;                       // floats per staged row (transpose)
constexpr int NBLK = 136;                      // 16*17/2 upper-triangular blocks

template <int TOLD_IS_I>
__global__ __launch_bounds__(512, 1) void cheb_gemm(
    const __half* __restrict__ Ahi_g, const __half* __restrict__ Alo_g,
    const __half* __restrict__ Bhi_g, const __half* __restrict__ Blo_g,
    const __half* __restrict__ Hold,  const __half* __restrict__ Lold,
    __half* __restrict__ Hout,        __half* __restrict__ Lout)
{
    extern __shared__ __align__(16) char smem[];
    const uint32_t sbase = smem_to_u32(smem);
    const int tid  = threadIdx.x;
    const int wid  = tid >> 5;
    const int lane = tid & 31;

    // triangular block decode: 136 blocks, i<=j
    int bid = blockIdx.x;
    int bi = 0;
    while (bid >= 16 - bi) { bid -= 16 - bi; ++bi; }
    const int bj = bi + bid;
    const int brow = bi * BM;
    const int bcol = bj * BM;

    const int wm = (wid >> 2) * 32;    // warp m origin
    const int wn = (wid & 3) * 32;     // warp n origin
    const int gid = lane >> 2;
    const int tig = lane & 3;

    // ldmatrix lane addressing (byte offsets within a tile)
    const uint32_t aoff = (uint32_t)((wm + (lane & 15)) * RS + ((lane >> 4) << 3)) * 2;
    const uint32_t boff = (uint32_t)((wn + ((lane >> 4) << 3) + (lane & 7)) * RS
                                     + (((lane >> 3) & 1) << 3)) * 2;

    // prefetch: 4 tiles x 512 chunks(16B); 1 chunk/tile/thread
    auto prefetch = [&](int it, int s) {
        const int k0 = it * BK;
        const uint32_t st = sbase + (uint32_t)s * STAGE_BYTES;
        const int r  = tid >> 2;
        const int c4 = tid & 3;
        const uint32_t so = (uint32_t)(r * RS + c4 * 8) * 2;
        const size_t ga = (size_t)(brow + r) * N + k0 + c4 * 8;
        const size_t gb = (size_t)(bcol + r) * N + k0 + c4 * 8;   // symmetric B
        CP_ASYNC16(st + 0 * TILE_BYTES + so, Ahi_g + ga);
        CP_ASYNC16(st + 1 * TILE_BYTES + so, Alo_g + ga);
        CP_ASYNC16(st + 2 * TILE_BYTES + so, Bhi_g + gb);
        CP_ASYNC16(st + 3 * TILE_BYTES + so, Blo_g + gb);
        CP_COMMIT();
    };

    float acc[2][4][4];
    #pragma unroll
    for (int mt = 0; mt < 2; ++mt)
        #pragma unroll
        for (int nt = 0; nt < 4; ++nt)
            acc[mt][nt][0] = acc[mt][nt][1] = acc[mt][nt][2] = acc[mt][nt][3] = 0.f;

    prefetch(0, 0);
    prefetch(1, 1);
    prefetch(2, 2);

    for (int it = 0; it < NITER; ++it) {
        const int s = it & 3;
        const int rem = NITER - 1 - it;
        if (rem >= 2)      { CP_WAIT(2); }
        else if (rem == 1) { CP_WAIT(1); }
        else               { CP_WAIT(0); }
        __syncthreads();
        // prefetch target (s+3)&3 was last READ at iter it-1; safe after barrier.
        if (it + 3 < NITER) prefetch(it + 3, (it + 3) & 3);

        const uint32_t st = sbase + (uint32_t)s * STAGE_BYTES;
        #pragma unroll
        for (int kk = 0; kk < 2; ++kk) {
            const uint32_t kb = (uint32_t)(kk * 16 * 2);
            uint32_t ah[2][4], al[2][4], bh[2][4], bl[2][4];
            #pragma unroll
            for (int mt = 0; mt < 2; ++mt) {
                const uint32_t a0 = st + aoff + (uint32_t)(mt * 16 * RS * 2) + kb;
                LDSM_X4(ah[mt], a0 + 0 * TILE_BYTES);
                LDSM_X4(al[mt], a0 + 1 * TILE_BYTES);
            }
            #pragma unroll
            for (int p = 0; p < 2; ++p) {
                const uint32_t b0 = st + boff + (uint32_t)(p * 16 * RS * 2) + kb;
                LDSM_X4(bh[p], b0 + 2 * TILE_BYTES);
                LDSM_X4(bl[p], b0 + 3 * TILE_BYTES);
            }
            // term-major order: 8 independent MMAs between same-acc reuses
            #pragma unroll
            for (int mt = 0; mt < 2; ++mt)
                #pragma unroll
                for (int nt = 0; nt < 4; ++nt)
                    MMA_F16(acc[mt][nt], ah[mt], &bh[nt >> 1][(nt & 1) * 2]);
            #pragma unroll
            for (int mt = 0; mt < 2; ++mt)
                #pragma unroll
                for (int nt = 0; nt < 4; ++nt)
                    MMA_F16(acc[mt][nt], ah[mt], &bl[nt >> 1][(nt & 1) * 2]);
            #pragma unroll
            for (int mt = 0; mt < 2; ++mt)
                #pragma unroll
                for (int nt = 0; nt < 4; ++nt)
                    MMA_F16(acc[mt][nt], al[mt], &bh[nt >> 1][(nt & 1) * 2]);
        }
    }
    __syncthreads();   // mainloop smem reads done before epilogue reuses smem

    // ---------------- epilogue ----------------
    float* stagef = reinterpret_cast<float*>(smem);   // 128 x 129 floats

    #pragma unroll
    for (int mt = 0; mt < 2; ++mt) {
        #pragma unroll
        for (int nt = 0; nt < 4; ++nt) {
            const int cl = wn + nt * 8 + 2 * tig;
            #pragma unroll
            for (int h = 0; h < 2; ++h) {
                const int rl = wm + mt * 16 + gid + h * 8;
                const size_t gi = (size_t)(brow + rl) * N + bcol + cl;
                float2 t;
                if (TOLD_IS_I) {
                    float d0 = (brow + rl == bcol + cl)     ? 1.0f : 0.0f;
                    float d1 = (brow + rl == bcol + cl + 1) ? 1.0f : 0.0f;
                    t.x = 2.0f * acc[mt][nt][2 * h]     - d0;
                    t.y = 2.0f * acc[mt][nt][2 * h + 1] - d1;
                } else {
                    float2 ho = __half22float2(*reinterpret_cast<const half2*>(Hold + gi));
                    float2 lo = __half22float2(*reinterpret_cast<const half2*>(Lold + gi));
                    t.x = 2.0f * acc[mt][nt][2 * h]     - (ho.x + lo.x);
                    t.y = 2.0f * acc[mt][nt][2 * h + 1] - (ho.y + lo.y);
                }
                __half hx = __float2half_rn(t.x);
                __half hy = __float2half_rn(t.y);
                __half lx = __float2half_rn(t.x - __half2float(hx));
                __half ly = __float2half_rn(t.y - __half2float(hy));
                *reinterpret_cast<half2*>(Hout + gi) = __halves2half2(hx, hy);
                *reinterpret_cast<half2*>(Lout + gi) = __halves2half2(lx, ly);
                stagef[rl * RS2 + cl]     = t.x;
                stagef[rl * RS2 + cl + 1] = t.y;
            }
        }
    }

    if (bj > bi) {
        __syncthreads();
        // mirror: out[(bcol+c)][brow+r] = t[r][c]
        #pragma unroll
        for (int q8 = 0; q8 < 8; ++q8) {
            const int c = wid * 8 + q8;
            const size_t obase = (size_t)(bcol + c) * N + brow;
            #pragma unroll
            for (int q = 0; q < 4; ++q) {
                const int r = q * 32 + lane;
                float t = stagef[r * RS2 + c];
                __half hx = __float2half_rn(t);
                __half lx = __float2half_rn(t - __half2float(hx));
                Hout[obase + r] = hx;
                Lout[obase + r] = lx;
            }
        }
    }
}

// ---------------------------------------------------------------------------
// Symmetric reduction: out[f] = diag(0.5*c0) + sum_{k=1..16} c_k*(H_k+L_k),
// reading ONLY the 136 upper-triangular tiles and mirroring the lower
// triangle via smem-staged transposed stores. 136 CTAs x 512 threads.
// Strip processing: 8 strips of 128x16 per tile; 4 elems x 8 filters per thr.
// ---------------------------------------------------------------------------
constexpr int RED_STAGE_FLOATS = 8 * 16 * 132;            // 16896
constexpr uint32_t RED_SMEM = RED_STAGE_FLOATS * 4;       // 67584 bytes

__global__ __launch_bounds__(512) void reduce_sym(const __half* __restrict__ HP,
                                                  float* __restrict__ out)
{
    extern __shared__ float stage[];   // [f*16 + c][132] -> stage[(f*16+c)*132 + r]
    __shared__ float sc[NCOEF * NFILT];
    const int tid = threadIdx.x;
    if (tid < NCOEF * NFILT) {
        float v = g_c[tid];
        if (tid < NFILT) v *= 0.5f;   // k == 0 entries
        sc[tid] = v;
    }
    __syncthreads();

    int bid = blockIdx.x;
    int bi = 0;
    while (bid >= 16 - bi) { bid -= 16 - bi; ++bi; }
    const int bj = bi + bid;
    const int brow = bi * 128;
    const int bcol = bj * 128;

    const int r     = tid >> 2;        // 0..127 local row
    const int cbase = (tid & 3) * 4;   // 0,4,8,12 local col within strip

    for (int s = 0; s < 8; ++s) {
        const int col0 = s * 16;
        float acc[NFILT][4];
        #pragma unroll
        for (int f = 0; f < NFILT; ++f)
            acc[f][0] = acc[f][1] = acc[f][2] = acc[f][3] = 0.f;

        // T_0 = I: diagonal contribution (diagonal blocks only)
        if (bi == bj) {
            const int d = r - col0 - cbase;
            if (d >= 0 && d < 4) {
                #pragma unroll
                for (int f = 0; f < NFILT; ++f)
                    acc[f][d] = sc[f];
            }
        }

        const size_t g = (size_t)(brow + r) * N + bcol + col0 + cbase;

        #pragma unroll 4
        for (int k = 1; k <= 16; ++k) {
            const __half* Hk = HP + (size_t)(2 * (k - 1)) * NN;
            const __half* Lk = Hk + NN;
            uint2 hu = __ldcs(reinterpret_cast<const uint2*>(Hk + g));
            uint2 lu = __ldcs(reinterpret_cast<const uint2*>(Lk + g));
            float2 h01 = __half22float2(*reinterpret_cast<half2*>(&hu.x));
            float2 h23 = __half22float2(*reinterpret_cast<half2*>(&hu.y));
            float2 l01 = __half22float2(*reinterpret_cast<half2*>(&lu.x));
            float2 l23 = __half22float2(*reinterpret_cast<half2*>(&lu.y));
            float t0 = h01.x + l01.x, t1 = h01.y + l01.y;
            float t2 = h23.x + l23.x, t3 = h23.y + l23.y;
            #pragma unroll
            for (int f = 0; f < NFILT; ++f) {
                const float cf = sc[k * NFILT + f];
                acc[f][0] += cf * t0; acc[f][1] += cf * t1;
                acc[f][2] += cf * t2; acc[f][3] += cf * t3;
            }
        }

        // direct (upper-triangle) store
        #pragma unroll
        for (int f = 0; f < NFILT; ++f) {
            float4 o = make_float4(acc[f][0], acc[f][1], acc[f][2], acc[f][3]);
            __stcs(reinterpret_cast<float4*>(&out[(size_t)f * NN + g]), o);
        }

        // mirror (lower triangle) via smem transpose
        if (bj > bi) {
            __syncthreads();
            #pragma unroll
            for (int f = 0; f < NFILT; ++f)
                #pragma unroll
                for (int e = 0; e < 4; ++e)
                    stage[(f * 16 + cbase + e) * 132 + r] = acc[f][e];
            __syncthreads();
            const int grow = (tid * 4) >> 7;    // 0..15 (strip col -> out row)
            const int gcol = (tid * 4) & 127;   // 0..124 (out col base)
            #pragma unroll
            for (int f = 0; f < NFILT; ++f) {
                float4 v = *reinterpret_cast<const float4*>(
                    &stage[(f * 16 + grow) * 132 + gcol]);
                __stcs(reinterpret_cast<float4*>(
                    &out[(size_t)f * NN + (size_t)(bcol + col0 + grow) * N + brow + gcol]), v);
            }
        }
    }
}

// ---------------------------------------------------------------------------
// Launch
// ---------------------------------------------------------------------------
extern "C" void kernel_launch(void* const* d_in, const int* in_sizes, int n_in,
                              void* d_out, int out_size) {
    const float* L    = (const float*)d_in[0];
    const float* taus = (const float*)d_in[1];
    float* out = (float*)d_out;

    void* pp = nullptr;
    cudaGetSymbolAddress(&pp, g_planes);
    __half* HP = (__half*)pp;

    static bool init_done = false;
    if (!init_done) {
        cudaFuncSetAttribute(cheb_gemm<0>, cudaFuncAttributeMaxDynamicSharedMemorySize, SMEM_BYTES);
        cudaFuncSetAttribute(cheb_gemm<1>, cudaFuncAttributeMaxDynamicSharedMemorySize, SMEM_BYTES);
        cudaFuncSetAttribute(reduce_sym,  cudaFuncAttributeMaxDynamicSharedMemorySize, RED_SMEM);
        init_done = true;
    }

    coeff_kernel<<<1, 256>>>(taus);
    const int vec_blocks = (int)(NN / 4 / 256);   // 4096
    init_split_kernel<<<vec_blocks, 256>>>(L, HP);

    // plane helpers (host side)
    auto pH = [&](int k) { return HP + (size_t)(2 * (k - 1)) * NN; };
    auto pL = [&](int k) { return HP + (size_t)(2 * (k - 1) + 1) * NN; };

    for (int k = 2; k < NCOEF; ++k) {
        const __half* Ah = pH(1);
        const __half* Al = pL(1);
        const __half* Bh = pH(k - 1);
        const __half* Bl = pL(k - 1);
        __half* Ho = pH(k);
        __half* Lo = pL(k);
        if (k == 2) {
            // T_old = T_0 = I (analytic); Hold/Lold unused
            cheb_gemm<1><<<NBLK, 512, SMEM_BYTES>>>(
                Ah, Al, Bh, Bl, pH(1), pL(1), Ho, Lo);
        } else {
            cheb_gemm<0><<<NBLK, 512, SMEM_BYTES>>>(
                Ah, Al, Bh, Bl, pH(k - 2), pL(k - 2), Ho, Lo);
        }
    }

    reduce_sym<<<NBLK, 512, RED_SMEM>>>(HP, out);
}